// round 2
// baseline (speedup 1.0000x reference)
#include <cuda_runtime.h>
#include <cuda_bf16.h>
#include <math.h>

#define SEQ_LEN 8192
#define D_MODEL 1024
#define N_HEADS 16
#define HEAD_DIM 64
#define MAX_ATTEND 16

// ---------------- scratch (alloc-free rule: __device__ globals) ----------------
__device__ float g_Q[SEQ_LEN * D_MODEL];
__device__ float g_K[SEQ_LEN * D_MODEL];
__device__ float g_V[SEQ_LEN * D_MODEL];
__device__ float g_A[SEQ_LEN * D_MODEL];

// ---------------- SGEMM: C[m,n] = sum_k A[m,k] * B[n,k]  (A @ B^T) -------------
// A: [M,K] row-major, B: [N,K] row-major (so B^T is K-contiguous too).
#define BM 128
#define BN 128
#define BK 16
#define TM 8
#define TN 8

__global__ __launch_bounds__(256, 2)
void sgemm_abt(const float* __restrict__ A, const float* __restrict__ B,
               float* __restrict__ C, int M, int N, int K) {
    const int cRow = blockIdx.y;
    const int cCol = blockIdx.x;
    const int tid  = threadIdx.x;

    __shared__ float As[BK][BM];
    __shared__ float Bs[BK][BN];

    const int threadCol = tid % (BN / TN);   // 0..15
    const int threadRow = tid / (BN / TN);   // 0..15

    // loading layout: 4 threads per row (4 x float4 = 16 floats per tile row)
    const int innerRow = tid / (BK / 4);     // 0..63
    const int innerCol = tid % (BK / 4);     // 0..3

    A += (size_t)cRow * BM * K;
    B += (size_t)cCol * BN * K;
    C += (size_t)cRow * BM * N + cCol * BN;

    float acc[TM][TN] = {{0.f}};
    float regM[TM], regN[TN];

    for (int bk = 0; bk < K; bk += BK) {
        #pragma unroll
        for (int off = 0; off < BM; off += 64) {
            float4 t = *(const float4*)(&A[(size_t)(innerRow + off) * K + bk + innerCol * 4]);
            As[innerCol * 4 + 0][innerRow + off] = t.x;
            As[innerCol * 4 + 1][innerRow + off] = t.y;
            As[innerCol * 4 + 2][innerRow + off] = t.z;
            As[innerCol * 4 + 3][innerRow + off] = t.w;
        }
        #pragma unroll
        for (int off = 0; off < BN; off += 64) {
            float4 t = *(const float4*)(&B[(size_t)(innerRow + off) * K + bk + innerCol * 4]);
            Bs[innerCol * 4 + 0][innerRow + off] = t.x;
            Bs[innerCol * 4 + 1][innerRow + off] = t.y;
            Bs[innerCol * 4 + 2][innerRow + off] = t.z;
            Bs[innerCol * 4 + 3][innerRow + off] = t.w;
        }
        __syncthreads();

        #pragma unroll
        for (int k = 0; k < BK; k++) {
            #pragma unroll
            for (int i = 0; i < TM; i++) regM[i] = As[k][threadRow * TM + i];
            #pragma unroll
            for (int j = 0; j < TN; j++) regN[j] = Bs[k][threadCol * TN + j];
            #pragma unroll
            for (int i = 0; i < TM; i++)
                #pragma unroll
                for (int j = 0; j < TN; j++)
                    acc[i][j] += regM[i] * regN[j];
        }
        __syncthreads();
    }

    #pragma unroll
    for (int i = 0; i < TM; i++) {
        #pragma unroll
        for (int j = 0; j < TN; j += 4) {
            float4 t = make_float4(acc[i][j], acc[i][j + 1], acc[i][j + 2], acc[i][j + 3]);
            *(float4*)(&C[(size_t)(threadRow * TM + i) * N + threadCol * TN + j]) = t;
        }
    }
}

// ---------------- sparse dilated attention ----------------
// One warp per (s, h). Each lane owns 2 head dims (64 dims / 32 lanes).
// Attended positions are structural: a=0 -> s, a>=1 -> s - 2^(a-1), valid iff >= 0.
__global__ __launch_bounds__(256)
void attn_kernel(const float* __restrict__ Q, const float* __restrict__ K,
                 const float* __restrict__ V, float* __restrict__ O) {
    const int gw   = (blockIdx.x * blockDim.x + threadIdx.x) >> 5;
    const int lane = threadIdx.x & 31;
    if (gw >= SEQ_LEN * N_HEADS) return;
    const int s = gw >> 4;
    const int h = gw & 15;
    const int col = h * HEAD_DIM + lane * 2;

    const float2 qv = *(const float2*)(&Q[(size_t)s * D_MODEL + col]);

    float sc[MAX_ATTEND];
    #pragma unroll
    for (int a = 0; a < MAX_ATTEND; a++) {
        const int off = a ? (1 << (a - 1)) : 0;
        const int p = s - off;
        if (p >= 0) {
            const float2 kv = *(const float2*)(&K[(size_t)p * D_MODEL + col]);
            float part = qv.x * kv.x + qv.y * kv.y;
            #pragma unroll
            for (int o = 16; o; o >>= 1)
                part += __shfl_xor_sync(0xffffffffu, part, o);
            sc[a] = part * 0.125f;   // 64^-0.5
        } else {
            sc[a] = -INFINITY;
        }
    }

    float mx = sc[0];
    #pragma unroll
    for (int a = 1; a < MAX_ATTEND; a++) mx = fmaxf(mx, sc[a]);

    float sum = 0.f, o0 = 0.f, o1 = 0.f;
    #pragma unroll
    for (int a = 0; a < MAX_ATTEND; a++) {
        const int off = a ? (1 << (a - 1)) : 0;
        const int p = s - off;
        if (p >= 0) {
            const float w = __expf(sc[a] - mx);
            sum += w;
            const float2 vv = *(const float2*)(&V[(size_t)p * D_MODEL + col]);
            o0 += w * vv.x;
            o1 += w * vv.y;
        }
    }
    const float inv = 1.f / sum;
    float2 ov = make_float2(o0 * inv, o1 * inv);
    *(float2*)(&O[(size_t)s * D_MODEL + col]) = ov;
}

// ---------------- launch ----------------
extern "C" void kernel_launch(void* const* d_in, const int* in_sizes, int n_in,
                              void* d_out, int out_size) {
    const float* x   = (const float*)d_in[0];
    const float* q_w = (const float*)d_in[1];
    const float* k_w = (const float*)d_in[2];
    const float* v_w = (const float*)d_in[3];
    const float* o_w = (const float*)d_in[4];
    float* out = (float*)d_out;

    float *Q, *K, *V, *Aout;
    cudaGetSymbolAddress((void**)&Q, g_Q);
    cudaGetSymbolAddress((void**)&K, g_K);
    cudaGetSymbolAddress((void**)&V, g_V);
    cudaGetSymbolAddress((void**)&Aout, g_A);

    dim3 gemmGrid(D_MODEL / BN, SEQ_LEN / BM);
    dim3 gemmBlock(256);

    sgemm_abt<<<gemmGrid, gemmBlock>>>(x, q_w, Q, SEQ_LEN, D_MODEL, D_MODEL);
    sgemm_abt<<<gemmGrid, gemmBlock>>>(x, k_w, K, SEQ_LEN, D_MODEL, D_MODEL);
    sgemm_abt<<<gemmGrid, gemmBlock>>>(x, v_w, V, SEQ_LEN, D_MODEL, D_MODEL);

    const int warps = SEQ_LEN * N_HEADS;
    attn_kernel<<<(warps * 32 + 255) / 256, 256>>>(Q, K, V, Aout);

    sgemm_abt<<<gemmGrid, gemmBlock>>>(Aout, o_w, out, SEQ_LEN, D_MODEL, D_MODEL);
}

// round 7
// speedup vs baseline: 3.0255x; 3.0255x over previous
#include <cuda_runtime.h>
#include <cuda_bf16.h>
#include <cstdint>
#include <math.h>

#define SEQ_LEN 8192
#define D_MODEL 1024
#define N_HEADS 16
#define HEAD_DIM 64
#define MAX_ATTEND 16

// ---------------- scratch (alloc-free rule: __device__ globals) ----------------
__device__ float g_Q[SEQ_LEN * D_MODEL];
__device__ float g_K[SEQ_LEN * D_MODEL];
__device__ float g_V[SEQ_LEN * D_MODEL];
__device__ float g_A[SEQ_LEN * D_MODEL];      // attn out, tf32-rounded
__device__ float g_Xc[SEQ_LEN * D_MODEL];     // x, tf32-rounded
__device__ float g_Wq[D_MODEL * D_MODEL];
__device__ float g_Wk[D_MODEL * D_MODEL];
__device__ float g_Wv[D_MODEL * D_MODEL];
__device__ float g_Wo[D_MODEL * D_MODEL];

// ================= portable PTX helpers (no sm_103a-only features) =================
__device__ __forceinline__ uint32_t smem_u32(const void* p) {
    uint32_t a;
    asm("{ .reg .u64 t; cvta.to.shared.u64 t, %1; cvt.u32.u64 %0, t; }" : "=r"(a) : "l"(p));
    return a;
}
__device__ __forceinline__ void cp_async16(uint32_t s, const void* g) {
    asm volatile("cp.async.cg.shared.global [%0], [%1], 16;" :: "r"(s), "l"(g) : "memory");
}
__device__ __forceinline__ float tf32_rna(float x) {
    uint32_t u;
    asm("cvt.rna.tf32.f32 %0, %1;" : "=r"(u) : "f"(x));
    return __uint_as_float(u);
}
__device__ __forceinline__ void ldsm_x4(uint32_t* r, uint32_t addr) {
    asm volatile("ldmatrix.sync.aligned.m8n8.x4.shared.b16 {%0,%1,%2,%3}, [%4];"
                 : "=r"(r[0]), "=r"(r[1]), "=r"(r[2]), "=r"(r[3]) : "r"(addr));
}
__device__ __forceinline__ void mma_tf32(float* c, const uint32_t* a, const uint32_t* b) {
    asm volatile("mma.sync.aligned.m16n8k8.row.col.f32.tf32.tf32.f32 "
                 "{%0,%1,%2,%3}, {%4,%5,%6,%7}, {%8,%9}, {%0,%1,%2,%3};"
                 : "+f"(c[0]), "+f"(c[1]), "+f"(c[2]), "+f"(c[3])
                 : "r"(a[0]), "r"(a[1]), "r"(a[2]), "r"(a[3]), "r"(b[0]), "r"(b[1]));
}

// ================= tf32 mma.sync GEMM: C[m,n] = sum_k A[m,k]*B[n,k] =================
// A: [M,1024] row-major (tf32-rounded fp32), B: [1024,1024] row-major (tf32-rounded).
// Tile 128x128x32, 8 warps as 2x4 -> warp tile 64x32. 4-stage cp.async pipeline.
#define GK 1024
#define GN 1024
#define KITERS 32
#define NSTAGES 4
#define ROW_BYTES 144                       // 32 floats + 4 pad
#define TILE_BYTES (128 * ROW_BYTES)        // 18432
#define STAGE_BYTES (2 * TILE_BYTES)        // A + B = 36864
#define GEMM_SMEM (NSTAGES * STAGE_BYTES)   // 147456

__global__ __launch_bounds__(256)
void tf32_mma_gemm(const float* __restrict__ A, const float* __restrict__ B,
                   float* __restrict__ C) {
    extern __shared__ char smem[];
    const uint32_t sbase = smem_u32(smem);
    const int tid = threadIdx.x;
    const int lane = tid & 31;
    const int wid = tid >> 5;
    const int wm = wid >> 2;       // 0..1
    const int wn = wid & 3;        // 0..3

    const char* Ab = (const char*)(A + (size_t)blockIdx.y * 128 * GK);
    const char* Bb = (const char*)(B + (size_t)blockIdx.x * 128 * GK);

    // ldmatrix per-thread base offsets
    const int q  = lane >> 3;      // matrix index 0..3
    const int r8 = lane & 7;       // row within matrix
    // A tile (m16 x k8): matrices {rows0-7 k0-3, rows8-15 k0-3, rows0-7 k4-7, rows8-15 k4-7}
    const uint32_t a_off = (uint32_t)((wm * 64 + (q & 1) * 8 + r8) * ROW_BYTES + (q >> 1) * 16);
    // B pair (two n8 tiles x k8): matrices {n0-7 k0-3, n0-7 k4-7, n8-15 k0-3, n8-15 k4-7}
    const uint32_t b_off = (uint32_t)(TILE_BYTES + (wn * 32 + (q >> 1) * 8 + r8) * ROW_BYTES + (q & 1) * 16);

    float acc[4][4][4];
    #pragma unroll
    for (int i = 0; i < 4; i++)
        #pragma unroll
        for (int j = 0; j < 4; j++)
            #pragma unroll
            for (int r = 0; r < 4; r++) acc[i][j][r] = 0.f;

    auto load_stage = [&](int kc, int buf) {
        const uint32_t sA = sbase + buf * STAGE_BYTES;
        const uint32_t sB = sA + TILE_BYTES;
        const size_t kbyte = (size_t)kc * 128;
        #pragma unroll
        for (int j = 0; j < 4; j++) {
            const int c = tid + j * 256;        // 0..1023
            const int row = c >> 3;
            const int cc  = c & 7;
            const uint32_t so = (uint32_t)(row * ROW_BYTES + cc * 16);
            const size_t go = (size_t)row * (GK * 4) + kbyte + cc * 16;
            cp_async16(sA + so, Ab + go);
            cp_async16(sB + so, Bb + go);
        }
    };

    #pragma unroll
    for (int s = 0; s < NSTAGES - 1; s++) {
        load_stage(s, s);
        asm volatile("cp.async.commit_group;" ::: "memory");
    }

    for (int j = 0; j < KITERS; j++) {
        asm volatile("cp.async.wait_group 2;" ::: "memory");
        __syncthreads();

        if (j + NSTAGES - 1 < KITERS) load_stage(j + NSTAGES - 1, (j + NSTAGES - 1) & (NSTAGES - 1));
        asm volatile("cp.async.commit_group;" ::: "memory");

        const uint32_t sb = sbase + (j & (NSTAGES - 1)) * STAGE_BYTES;
        #pragma unroll
        for (int ks = 0; ks < 4; ks++) {
            uint32_t ka[4][4];
            uint32_t kb[4][2];
            #pragma unroll
            for (int mi = 0; mi < 4; mi++)
                ldsm_x4(ka[mi], sb + a_off + mi * (16 * ROW_BYTES) + ks * 32);
            #pragma unroll
            for (int n2 = 0; n2 < 2; n2++) {
                uint32_t t[4];
                ldsm_x4(t, sb + b_off + n2 * (16 * ROW_BYTES) + ks * 32);
                kb[2 * n2][0] = t[0]; kb[2 * n2][1] = t[1];
                kb[2 * n2 + 1][0] = t[2]; kb[2 * n2 + 1][1] = t[3];
            }
            #pragma unroll
            for (int mi = 0; mi < 4; mi++)
                #pragma unroll
                for (int nj = 0; nj < 4; nj++)
                    mma_tf32(acc[mi][nj], ka[mi], kb[nj]);
        }
    }

    float* Cb = C + (size_t)blockIdx.y * 128 * GN + blockIdx.x * 128;
    const int trow = lane >> 2;
    const int tcol = (lane & 3) * 2;
    #pragma unroll
    for (int mi = 0; mi < 4; mi++) {
        #pragma unroll
        for (int nj = 0; nj < 4; nj++) {
            const int row = wm * 64 + mi * 16 + trow;
            const int col = wn * 32 + nj * 8 + tcol;
            *(float2*)(Cb + (size_t)row * GN + col)       = make_float2(acc[mi][nj][0], acc[mi][nj][1]);
            *(float2*)(Cb + (size_t)(row + 8) * GN + col) = make_float2(acc[mi][nj][2], acc[mi][nj][3]);
        }
    }
}

// ---------------- tf32 rounding pass (unbiased rna, for accuracy) ----------------
__global__ __launch_bounds__(256)
void cvt_tf32_kernel(const float* __restrict__ in, float* __restrict__ out, int n4) {
    const int i = blockIdx.x * blockDim.x + threadIdx.x;
    if (i >= n4) return;
    float4 v = ((const float4*)in)[i];
    v.x = tf32_rna(v.x); v.y = tf32_rna(v.y);
    v.z = tf32_rna(v.z); v.w = tf32_rna(v.w);
    ((float4*)out)[i] = v;
}

// ---------------- sparse dilated attention ----------------
// One warp per (s, h). Attended positions structural: a=0 -> s, a>=1 -> s - 2^(a-1).
__global__ __launch_bounds__(256)
void attn_kernel(const float* __restrict__ Q, const float* __restrict__ K,
                 const float* __restrict__ V, float* __restrict__ O) {
    const int gw   = (blockIdx.x * blockDim.x + threadIdx.x) >> 5;
    const int lane = threadIdx.x & 31;
    if (gw >= SEQ_LEN * N_HEADS) return;
    const int s = gw >> 4;
    const int h = gw & 15;
    const int col = h * HEAD_DIM + lane * 2;

    const float2 qv = *(const float2*)(&Q[(size_t)s * D_MODEL + col]);

    float sc[MAX_ATTEND];
    #pragma unroll
    for (int a = 0; a < MAX_ATTEND; a++) {
        const int off = a ? (1 << (a - 1)) : 0;
        const int p = s - off;
        if (p >= 0) {
            const float2 kv = *(const float2*)(&K[(size_t)p * D_MODEL + col]);
            float part = qv.x * kv.x + qv.y * kv.y;
            #pragma unroll
            for (int o = 16; o; o >>= 1)
                part += __shfl_xor_sync(0xffffffffu, part, o);
            sc[a] = part * 0.125f;
        } else {
            sc[a] = -INFINITY;
        }
    }

    float mx = sc[0];
    #pragma unroll
    for (int a = 1; a < MAX_ATTEND; a++) mx = fmaxf(mx, sc[a]);

    float sum = 0.f, o0 = 0.f, o1 = 0.f;
    #pragma unroll
    for (int a = 0; a < MAX_ATTEND; a++) {
        const int off = a ? (1 << (a - 1)) : 0;
        const int p = s - off;
        if (p >= 0) {
            const float w = __expf(sc[a] - mx);
            sum += w;
            const float2 vv = *(const float2*)(&V[(size_t)p * D_MODEL + col]);
            o0 += w * vv.x;
            o1 += w * vv.y;
        }
    }
    const float inv = 1.f / sum;
    // emit tf32-rounded (unbiased) so the o-proj GEMM sees rna inputs
    float2 ov = make_float2(tf32_rna(o0 * inv), tf32_rna(o1 * inv));
    *(float2*)(&O[(size_t)s * D_MODEL + col]) = ov;
}

// ---------------- launch ----------------
extern "C" void kernel_launch(void* const* d_in, const int* in_sizes, int n_in,
                              void* d_out, int out_size) {
    const float* x   = (const float*)d_in[0];
    const float* q_w = (const float*)d_in[1];
    const float* k_w = (const float*)d_in[2];
    const float* v_w = (const float*)d_in[3];
    const float* o_w = (const float*)d_in[4];
    float* out = (float*)d_out;

    float *Q, *K, *V, *Aout, *Xc, *Wq, *Wk, *Wv, *Wo;
    cudaGetSymbolAddress((void**)&Q, g_Q);
    cudaGetSymbolAddress((void**)&K, g_K);
    cudaGetSymbolAddress((void**)&V, g_V);
    cudaGetSymbolAddress((void**)&Aout, g_A);
    cudaGetSymbolAddress((void**)&Xc, g_Xc);
    cudaGetSymbolAddress((void**)&Wq, g_Wq);
    cudaGetSymbolAddress((void**)&Wk, g_Wk);
    cudaGetSymbolAddress((void**)&Wv, g_Wv);
    cudaGetSymbolAddress((void**)&Wo, g_Wo);

    cudaFuncSetAttribute(tf32_mma_gemm, cudaFuncAttributeMaxDynamicSharedMemorySize, GEMM_SMEM);

    // tf32-round inputs (unbiased rna)
    const int x4 = SEQ_LEN * D_MODEL / 4;     // 2M float4
    const int w4 = D_MODEL * D_MODEL / 4;     // 256K float4
    cvt_tf32_kernel<<<(x4 + 255) / 256, 256>>>(x, Xc, x4);
    cvt_tf32_kernel<<<(w4 + 255) / 256, 256>>>(q_w, Wq, w4);
    cvt_tf32_kernel<<<(w4 + 255) / 256, 256>>>(k_w, Wk, w4);
    cvt_tf32_kernel<<<(w4 + 255) / 256, 256>>>(v_w, Wv, w4);
    cvt_tf32_kernel<<<(w4 + 255) / 256, 256>>>(o_w, Wo, w4);

    dim3 gemmGrid(GN / 128, SEQ_LEN / 128);   // (8, 64)
    dim3 gemmBlock(256);

    tf32_mma_gemm<<<gemmGrid, gemmBlock, GEMM_SMEM>>>(Xc, Wq, Q);
    tf32_mma_gemm<<<gemmGrid, gemmBlock, GEMM_SMEM>>>(Xc, Wk, K);
    tf32_mma_gemm<<<gemmGrid, gemmBlock, GEMM_SMEM>>>(Xc, Wv, V);

    const int warps = SEQ_LEN * N_HEADS;
    attn_kernel<<<(warps * 32 + 255) / 256, 256>>>(Q, K, V, Aout);

    tf32_mma_gemm<<<gemmGrid, gemmBlock, GEMM_SMEM>>>(Aout, Wo, out);
}